// round 16
// baseline (speedup 1.0000x reference)
#include <cuda_runtime.h>
#include <cuda_fp16.h>

// PatchMerging fused (HMMA fp16, double-buffered 1-sync pipeline, fully unrolled phases):
//   paired-octant float2 gather -> LN stats -> fp16 A (64-wide tile)
//   -> mma.sync GEMM (768 x 192) -> LN-folded epilogue -> coalesced transposed store
// x:(2,96,32,64,64) f32 ; gamma,beta:(768,) ; w_red:(768,192) ; out:(2,192,16,32,32) f32
//
// acc[t,o] = sum_k y[t,k]*(gamma_k W[k,o])  (A,B fp16, fp32 accum)
// out[t,o] = rstd_t*(acc - mu_t*g[o]) + c[o]
//
// Phase f (=3g+sub) stages k-tiles 6g+sub (octant 2g) and 6g+sub+3 (octant 2g+1),
// both halves of one float2 gather, as a 64-wide A/B tile; mma does 4 k16-steps.
// Pipeline per phase: cp B(f+1) | STS A(f+1) | LDG v(f+2) | mma(f) | wait | sync.

#define KTOT 768
#define NOUT 192
#define TM   64

#define XS_C 131072
#define XS_D 4096
#define XS_H 64
#define XS_B 12582912
#define OS_O 16384
#define OS_B 3145728
#define OS_D 1024
#define OS_H 32

// smem rows: 64 fp16 = 128B + 16B pad = 144
#define TROW 144
#define A_OFF(b) ((b) * 9216)               // 64*144 each, double buffered
#define B_OFF(b) (18432 + (b) * 27648)      // 192*144 each, double buffered
#define DSMEM_BYTES 73728                   // (epilogue tile fits)

#define PREP_KROWS 4
#define PREP_BLKS  192

__device__ float g_gv[NOUT];
__device__ float g_cv[NOUT];
__device__ float g_part_g[PREP_BLKS * NOUT];
__device__ float g_part_c[PREP_BLKS * NOUT];
__device__ __align__(16) __half g_Bt_h[NOUT * KTOT];   // [n][k] gamma-scaled fp16

// ---------------- helpers ----------------
__device__ __forceinline__ unsigned smem_u32(const void* p) {
    unsigned a;
    asm("{ .reg .u64 t; cvta.to.shared.u64 t, %1; cvt.u32.u64 %0, t; }" : "=r"(a) : "l"(p));
    return a;
}
__device__ __forceinline__ void ldsm4(unsigned& r0, unsigned& r1, unsigned& r2, unsigned& r3,
                                      unsigned addr) {
    asm volatile("ldmatrix.sync.aligned.m8n8.x4.shared.b16 {%0,%1,%2,%3}, [%4];"
                 : "=r"(r0), "=r"(r1), "=r"(r2), "=r"(r3) : "r"(addr));
}
__device__ __forceinline__ void mma_f16(float* c, const unsigned* a, unsigned b0, unsigned b1) {
    asm volatile(
        "mma.sync.aligned.m16n8k16.row.col.f32.f16.f16.f32 "
        "{%0,%1,%2,%3}, {%4,%5,%6,%7}, {%8,%9}, {%0,%1,%2,%3};"
        : "+f"(c[0]), "+f"(c[1]), "+f"(c[2]), "+f"(c[3])
        : "r"(a[0]), "r"(a[1]), "r"(a[2]), "r"(a[3]), "r"(b0), "r"(b1));
}
__device__ __forceinline__ unsigned pack_h2(float lo, float hi) {
    __half2 h = __floats2half2_rn(lo, hi);       // single cvt.rn.f16x2.f32
    return *(unsigned*)&h;
}
#define CP_ASYNC16(s, g) \
    asm volatile("cp.async.cg.shared.global [%0], [%1], 16;" :: "r"(s), "l"(g))
#define CP_COMMIT() asm volatile("cp.async.commit_group;")

// ---------------- prep kernels ----------------
__global__ __launch_bounds__(256)
void prep1(const float* __restrict__ w, const float* __restrict__ gamma,
           const float* __restrict__ beta) {
    __shared__ float ts[PREP_KROWS][NOUT + 1];
    __shared__ float gam_s[PREP_KROWS], bet_s[PREP_KROWS];
    const int tid = threadIdx.x;
    const int k0  = blockIdx.x * PREP_KROWS;

    if (tid < PREP_KROWS) {
        gam_s[tid] = gamma[k0 + tid];
        bet_s[tid] = beta[k0 + tid];
    }
#pragma unroll
    for (int i = tid; i < PREP_KROWS * NOUT; i += 256) {
        int r = i / NOUT, n = i - r * NOUT;
        ts[r][n] = w[(k0 + r) * NOUT + n];
    }
    __syncthreads();

    if (tid < NOUT) {
        float g = 0.f, c = 0.f;
        __half hbuf[PREP_KROWS];
#pragma unroll
        for (int r = 0; r < PREP_KROWS; ++r) {
            float wv = ts[r][tid];
            g += gam_s[r] * wv;
            c += bet_s[r] * wv;
            hbuf[r] = __float2half_rn(gam_s[r] * wv);
        }
        g_part_g[blockIdx.x * NOUT + tid] = g;
        g_part_c[blockIdx.x * NOUT + tid] = c;
        *(uint2*)(&g_Bt_h[tid * KTOT + k0]) = *(uint2*)hbuf;
    }
}

__global__ void prep2() {
    int o = threadIdx.x;   // 192 threads
    float g = 0.f, c = 0.f;
#pragma unroll 8
    for (int b = 0; b < PREP_BLKS; ++b) {
        g += g_part_g[b * NOUT + o];
        c += g_part_c[b * NOUT + o];
    }
    g_gv[o] = g;
    g_cv[o] = c;
}

// ---------------- main kernel ----------------
extern __shared__ __align__(16) unsigned char dsm[];

__global__ __launch_bounds__(256, 2)
void pm_kernel(const float* __restrict__ x, float* __restrict__ out) {
    __shared__ float red[512];
    __shared__ float mu_s[TM], rs_s[TM];
    __shared__ float gv_s[NOUT], cv_s[NOUT];

    const int tid = threadIdx.x, wid = tid >> 5, lane = tid & 31;
    const unsigned dbase = smem_u32(dsm);

    if (tid < NOUT) { gv_s[tid] = g_gv[tid]; cv_s[tid] = g_cv[tid]; }

    // gather mapping: thread (tl, kk0): token tl, 8 float2 per phase (rows kk0*8..+7)
    const int tl  = tid & (TM - 1);
    const int kk0 = tid >> 6;
    const int t   = blockIdx.x * TM + tl;
    const int wx = t & 31, hy = (t >> 5) & 31, dz = (t >> 10) & 15, bb = t >> 14;
    const float* xb = x + bb * XS_B + (2 * dz) * XS_D + (2 * hy) * XS_H + 2 * wx;

    // warp GEMM tile: m32 x n48
    const int warpM = (wid & 1) * 32;
    const int warpN = (wid >> 1) * 48;

    float acc[2][6][4];
#pragma unroll
    for (int mi = 0; mi < 2; ++mi)
#pragma unroll
        for (int nj = 0; nj < 6; ++nj)
#pragma unroll
            for (int e = 0; e < 4; ++e) acc[mi][nj][e] = 0.f;

    float sum = 0.f, sq = 0.f;
    float v[8], vy[8];

    // gather phase f: octant pair (2g, 2g+1), c0 = 32*(f%3)  [f compile-time when unrolled]
#define GATHER(f)                                                                   \
    do {                                                                            \
        const int _g = (f) / 3, _s = (f) - 3 * _g;                                  \
        const int _p = 2 * _g;                                                      \
        const int _offs = (_p >> 2) * XS_D + ((_p >> 1) & 1) * XS_H + (_s * 32) * XS_C; \
        _Pragma("unroll")                                                           \
        for (int i = 0; i < 8; ++i) {                                               \
            float2 xv = *(const float2*)(xb + (kk0 * 8 + i) * XS_C + _offs);        \
            v[i] = xv.x;                                                            \
            vy[i] = xv.y;                                                           \
        }                                                                           \
    } while (0)

#define STAGE_A(buf)                                                                \
    do {                                                                            \
        unsigned hx[4], hy4[4];                                                     \
        _Pragma("unroll")                                                           \
        for (int i = 0; i < 4; ++i) {                                               \
            float a = v[2 * i], b = v[2 * i + 1];                                   \
            float a2 = vy[2 * i], b2 = vy[2 * i + 1];                               \
            sum += a + b + a2 + b2;                                                 \
            sq  += a * a + b * b + a2 * a2 + b2 * b2;                               \
            hx[i]  = pack_h2(a, b);                                                 \
            hy4[i] = pack_h2(a2, b2);                                               \
        }                                                                           \
        unsigned rb = tl * TROW + kk0 * 16;                                         \
        *(uint4*)(dsm + A_OFF(buf) + rb)      = make_uint4(hx[0], hx[1], hx[2], hx[3]);      \
        *(uint4*)(dsm + A_OFF(buf) + rb + 64) = make_uint4(hy4[0], hy4[1], hy4[2], hy4[3]);  \
    } while (0)

#define CP_B(f, buf)                                                                \
    do {                                                                            \
        const int _g = (f) / 3, _s = (f) - 3 * _g;                                  \
        const int _kt = 6 * _g + _s;                                                \
        _Pragma("unroll")                                                           \
        for (int j = 0; j < 6; ++j) {                                               \
            int idx = tid + 256 * j;                                                \
            int n = idx >> 3, ch = idx & 7;                                         \
            long goff = (long)n * (KTOT * 2) +                                      \
                        ((ch < 4) ? (_kt * 64 + ch * 16)                            \
                                  : ((_kt + 3) * 64 + (ch - 4) * 16));              \
            CP_ASYNC16(dbase + B_OFF(buf) + n * TROW + ch * 16,                     \
                       (const char*)g_Bt_h + goff);                                 \
        }                                                                           \
        CP_COMMIT();                                                                \
    } while (0)

    // ---- prologue: B cp.async first (L2 latency rides under gather DRAM latency) ----
    CP_B(0, 0);
    GATHER(0);
    STAGE_A(0);      // uses v(0)
    GATHER(1);
    asm volatile("cp.async.wait_group 0;");
    __syncthreads();

    // ---- 12 phases, one barrier each, fully unrolled (all offsets immediate) ----
#pragma unroll
    for (int p = 0; p < 12; ++p) {
        const int buf = p & 1;

        if (p < 11) {
            CP_B(p + 1, buf ^ 1);     // into B[buf^1]: last read at mma(p-1), synced
            STAGE_A(buf ^ 1);         // A(p+1) from v(p+1): same safety argument
            if (p + 2 < 12) GATHER(p + 2);
        }

        // mma(p): 4 k16-steps on A[buf], B[buf]
        const unsigned bh_base = dbase + B_OFF(buf);
#pragma unroll
        for (int ks = 0; ks < 4; ++ks) {
            unsigned a_h[2][4];
#pragma unroll
            for (int mi = 0; mi < 2; ++mi) {
                unsigned row = warpM + mi * 16 + (lane & 15);
                unsigned off = row * TROW + (ks * 2 + (lane >> 4)) * 16;
                ldsm4(a_h[mi][0], a_h[mi][1], a_h[mi][2], a_h[mi][3],
                      dbase + A_OFF(buf) + off);
            }
#pragma unroll
            for (int j = 0; j < 3; ++j) {
                unsigned brow = warpN + j * 16 + ((lane >> 4) << 3) + (lane & 7);
                unsigned boff = brow * TROW + (ks * 2 + ((lane >> 3) & 1)) * 16;
                unsigned b0, b1, b2, b3;
                ldsm4(b0, b1, b2, b3, bh_base + boff);
#pragma unroll
                for (int mi = 0; mi < 2; ++mi) {
                    mma_f16(acc[mi][j * 2],     a_h[mi], b0, b1);
                    mma_f16(acc[mi][j * 2 + 1], a_h[mi], b2, b3);
                }
            }
        }

        if (p < 11) { asm volatile("cp.async.wait_group 0;"); }
        __syncthreads();
    }

    // ---- LN stats reduction (4 partials per token) ----
    red[tid] = sum;
    red[tid + 256] = sq;
    __syncthreads();
    if (tid < TM) {
        float s  = red[tid] + red[tid + 64] + red[tid + 128] + red[tid + 192];
        float ss = red[tid + 256] + red[tid + 320] + red[tid + 384] + red[tid + 448];
        float mu  = s * (1.f / 768.f);
        float var = ss * (1.f / 768.f) - mu * mu;
        mu_s[tid] = mu;
        rs_s[tid] = rsqrtf(var + 1e-5f);
    }
    __syncthreads();

    // ---- epilogue: LN fold + transpose via smem, float2 coalesced stores ----
    float* etile = (float*)dsm;   // [96][68] f32 = 26112 B
    const int T0 = blockIdx.x * TM;
    const int base0 = (T0 >> 14) * OS_B + ((T0 >> 10) & 15) * OS_D + ((T0 >> 5) & 31) * OS_H;
    const int lane4 = lane >> 2, lpair = (lane & 3) * 2;

#pragma unroll
    for (int phh = 0; phh < 2; ++phh) {
        if ((warpN / 96) == phh) {
            const int nb = warpN - phh * 96;
#pragma unroll
            for (int mi = 0; mi < 2; ++mi)
#pragma unroll
                for (int nj = 0; nj < 6; ++nj) {
                    int nloc = nb + nj * 8 + lpair;
                    int o = phh * 96 + nloc;
                    float g0 = gv_s[o], g1 = gv_s[o + 1];
                    float c0 = cv_s[o], c1 = cv_s[o + 1];
#pragma unroll
                    for (int e = 0; e < 2; ++e) {
                        int row = warpM + mi * 16 + lane4 + e * 8;
                        float mu = mu_s[row], rs = rs_s[row];
                        etile[nloc * 68 + row]       = rs * (acc[mi][nj][2 * e]     - mu * g0) + c0;
                        etile[(nloc + 1) * 68 + row] = rs * (acc[mi][nj][2 * e + 1] - mu * g1) + c1;
                    }
                }
        }
        __syncthreads();
#pragma unroll
        for (int j = 0; j < 12; ++j) {
            int idx = tid + 256 * j;          // 3072 float2 chunks: 96 rows x 32
            int ol = idx >> 5, p2 = idx & 31;
            float2 val = make_float2(etile[ol * 68 + 2 * p2], etile[ol * 68 + 2 * p2 + 1]);
            *(float2*)(out + base0 + (phh * 96 + ol) * OS_O + 2 * p2) = val;
        }
        __syncthreads();
    }
}

extern "C" void kernel_launch(void* const* d_in, const int* in_sizes, int n_in,
                              void* d_out, int out_size) {
    const float* x     = (const float*)d_in[0];
    const float* gamma = (const float*)d_in[1];
    const float* beta  = (const float*)d_in[2];
    const float* w     = (const float*)d_in[3];
    float* out = (float*)d_out;

    cudaFuncSetAttribute(pm_kernel, cudaFuncAttributeMaxDynamicSharedMemorySize, DSMEM_BYTES);

    prep1<<<PREP_BLKS, 256>>>(w, gamma, beta);
    prep2<<<1, NOUT>>>();
    pm_kernel<<<32768 / TM, 256, DSMEM_BYTES>>>(x, out);
}